// round 1
// baseline (speedup 1.0000x reference)
#include <cuda_runtime.h>
#include <math.h>

#define D_MODEL 1024
#define D_FF    4096
#define BATCH   8
#define SEQ     2048
#define M_TOT   (BATCH * SEQ)   // 16384

// ---------------- scratch (allocation-free: __device__ globals) ----------------
__device__ float g_C0[(long long)M_TOT * D_FF];   // 256 MB: X@Wi0 then H=gelu*lin
__device__ float g_C1[(long long)M_TOT * D_FF];   // 256 MB: X@Wi1
__device__ float g_O0[(long long)M_TOT * D_MODEL]; // 64 MB: expert_out
__device__ float g_O1[(long long)M_TOT * D_MODEL]; // 64 MB: share_out
__device__ float g_W[BATCH * 2];                   // gate weights

// ---------------- SGEMM: C[M,N] = A[M,K] @ B[K,N], row-major -------------------
// Per-batch expert selection: rows [b*SEQ,(b+1)*SEQ) use B + labels[b]*expert_stride.
// labels == nullptr -> single shared weight (offset 0).
#define BM 128
#define BN 128
#define BK 8
#define TM 8
#define TN 8

__global__ __launch_bounds__(256)
void sgemm_kernel(const float* __restrict__ A, const float* __restrict__ B,
                  float* __restrict__ C, int N, int K,
                  const int* __restrict__ labels, long long expert_stride)
{
    __shared__ float As[BK][BM];
    __shared__ float Bs[BK][BN];

    const int tid  = threadIdx.x;
    const int tcol = tid % (BN / TN);   // 0..15
    const int trow = tid / (BN / TN);   // 0..15

    const int rowBase = blockIdx.y * BM;
    const int colBase = blockIdx.x * BN;

    const float* Bp = B;
    if (labels) {
        int b = rowBase / SEQ;          // BM=128 divides SEQ=2048: tiles never straddle
        Bp += (long long)labels[b] * expert_stride;
    }

    // A tile load mapping: one float4 per thread (128 rows x 8 cols = 256 float4)
    const int aRow  = tid >> 1;         // 0..127
    const int aCol4 = (tid & 1) * 4;    // 0 or 4
    // B tile load mapping: 8 rows x 128 cols = 256 float4
    const int bRow  = tid >> 5;         // 0..7
    const int bCol4 = (tid & 31) * 4;   // 0..124

    float acc[TM][TN];
#pragma unroll
    for (int i = 0; i < TM; i++)
#pragma unroll
        for (int j = 0; j < TN; j++) acc[i][j] = 0.f;

    for (int k0 = 0; k0 < K; k0 += BK) {
        // load A tile (transpose into As[k][m])
        float4 av = *reinterpret_cast<const float4*>(
            &A[(long long)(rowBase + aRow) * K + k0 + aCol4]);
        As[aCol4 + 0][aRow] = av.x;
        As[aCol4 + 1][aRow] = av.y;
        As[aCol4 + 2][aRow] = av.z;
        As[aCol4 + 3][aRow] = av.w;
        // load B tile
        *reinterpret_cast<float4*>(&Bs[bRow][bCol4]) =
            *reinterpret_cast<const float4*>(
                &Bp[(long long)(k0 + bRow) * N + colBase + bCol4]);
        __syncthreads();

#pragma unroll
        for (int kk = 0; kk < BK; kk++) {
            float af[TM], bf[TN];
#pragma unroll
            for (int i = 0; i < TM; i++) af[i] = As[kk][trow * TM + i];
#pragma unroll
            for (int j = 0; j < TN; j++) bf[j] = Bs[kk][tcol * TN + j];
#pragma unroll
            for (int i = 0; i < TM; i++)
#pragma unroll
                for (int j = 0; j < TN; j++) acc[i][j] = fmaf(af[i], bf[j], acc[i][j]);
        }
        __syncthreads();
    }

#pragma unroll
    for (int i = 0; i < TM; i++) {
        long long crow = (long long)(rowBase + trow * TM + i) * N + colBase + tcol * TN;
#pragma unroll
        for (int j = 0; j < TN; j += 4) {
            float4 v = make_float4(acc[i][j], acc[i][j + 1], acc[i][j + 2], acc[i][j + 3]);
            *reinterpret_cast<float4*>(&C[crow + j]) = v;
        }
    }
}

// ---------------- gelu(tanh approx) * linear, in place into C0 -----------------
__device__ __forceinline__ float gelu_tanh(float x) {
    float x3 = x * x * x;
    return 0.5f * x * (1.f + tanhf(0.7978845608028654f * (x + 0.044715f * x3)));
}

__global__ __launch_bounds__(256)
void act_kernel(float* __restrict__ C0, const float* __restrict__ C1, long long n)
{
    long long i = ((long long)blockIdx.x * blockDim.x + threadIdx.x) * 4;
    if (i >= n) return;
    float4 a = *reinterpret_cast<const float4*>(&C0[i]);
    float4 b = *reinterpret_cast<const float4*>(&C1[i]);
    a.x = gelu_tanh(a.x) * b.x;
    a.y = gelu_tanh(a.y) * b.y;
    a.z = gelu_tanh(a.z) * b.z;
    a.w = gelu_tanh(a.w) * b.w;
    *reinterpret_cast<float4*>(&C0[i]) = a;
}

// ---------------- gate: weights[b][2] from first-token rows --------------------
__global__ __launch_bounds__(256)
void gate_kernel(const float* __restrict__ O0, const float* __restrict__ O1,
                 const float* __restrict__ g0, const float* __restrict__ g1,
                 float* __restrict__ w)
{
    int b = blockIdx.x;
    const float* r0 = O0 + (long long)b * SEQ * D_MODEL;  // expert_out[b,0,:]
    const float* r1 = O1 + (long long)b * SEQ * D_MODEL;  // share_out[b,0,:]

    float h[4] = {0.f, 0.f, 0.f, 0.f};
    for (int k = 0; k < 2 * D_MODEL; k++) {
        float xin = (k < D_MODEL) ? r0[k] : r1[k - D_MODEL];
        const float* grow = g0 + (long long)k * D_MODEL;
#pragma unroll
        for (int u = 0; u < 4; u++)
            h[u] = fmaf(xin, grow[threadIdx.x + 256 * u], h[u]);
    }

    float l0 = 0.f, l1 = 0.f;
#pragma unroll
    for (int u = 0; u < 4; u++) {
        int j = threadIdx.x + 256 * u;
        float hr = fmaxf(h[u], 0.f);
        l0 = fmaf(hr, g1[j * 2 + 0], l0);
        l1 = fmaf(hr, g1[j * 2 + 1], l1);
    }

    __shared__ float red0[256], red1[256];
    red0[threadIdx.x] = l0;
    red1[threadIdx.x] = l1;
    __syncthreads();
    for (int s = 128; s > 0; s >>= 1) {
        if (threadIdx.x < s) {
            red0[threadIdx.x] += red0[threadIdx.x + s];
            red1[threadIdx.x] += red1[threadIdx.x + s];
        }
        __syncthreads();
    }
    if (threadIdx.x == 0) {
        float a = red0[0], c = red1[0];
        float m  = fmaxf(a, c);
        float e0 = expf(a - m), e1 = expf(c - m);
        float inv = 1.f / (e0 + e1);
        w[b * 2 + 0] = e0 * inv;
        w[b * 2 + 1] = e1 * inv;
    }
}

// ---------------- combine: out = O0*w0[b] + O1*w1[b] ---------------------------
__global__ __launch_bounds__(256)
void combine_kernel(const float* __restrict__ O0, const float* __restrict__ O1,
                    const float* __restrict__ w, float* __restrict__ out)
{
    long long i = ((long long)blockIdx.x * blockDim.x + threadIdx.x) * 4;
    int b = (int)(i / ((long long)SEQ * D_MODEL));
    float w0 = w[b * 2 + 0], w1 = w[b * 2 + 1];
    float4 a = *reinterpret_cast<const float4*>(&O0[i]);
    float4 c = *reinterpret_cast<const float4*>(&O1[i]);
    a.x = a.x * w0 + c.x * w1;
    a.y = a.y * w0 + c.y * w1;
    a.z = a.z * w0 + c.z * w1;
    a.w = a.w * w0 + c.w * w1;
    *reinterpret_cast<float4*>(&out[i]) = a;
}

// ---------------- launch -------------------------------------------------------
extern "C" void kernel_launch(void* const* d_in, const int* in_sizes, int n_in,
                              void* d_out, int out_size)
{
    const float* X    = (const float*)d_in[0];  // [8,2048,1024]
    const int*   lbl  = (const int*)  d_in[1];  // [8]
    const float* Wi0  = (const float*)d_in[2];  // [5,1024,4096]
    const float* Wi1  = (const float*)d_in[3];
    const float* Wo   = (const float*)d_in[4];  // [5,4096,1024]
    const float* sWi0 = (const float*)d_in[5];
    const float* sWi1 = (const float*)d_in[6];
    const float* sWo  = (const float*)d_in[7];
    const float* G0   = (const float*)d_in[8];  // [2048,1024]
    const float* G1   = (const float*)d_in[9];  // [1024,2]
    float* out = (float*)d_out;

    float *C0, *C1, *O0, *O1, *W;
    cudaGetSymbolAddress((void**)&C0, g_C0);
    cudaGetSymbolAddress((void**)&C1, g_C1);
    cudaGetSymbolAddress((void**)&O0, g_O0);
    cudaGetSymbolAddress((void**)&O1, g_O1);
    cudaGetSymbolAddress((void**)&W,  g_W);

    const long long exp_stride = (long long)D_MODEL * D_FF; // == D_FF*D_MODEL
    dim3 blk(256);
    dim3 grid_up(D_FF / BN, M_TOT / BM);     // (32,128) — X@Wi*
    dim3 grid_dn(D_MODEL / BN, M_TOT / BM);  // (8,128)  — H@Wo
    const long long nFF = (long long)M_TOT * D_FF;      // 67108864
    const long long nD  = (long long)M_TOT * D_MODEL;   // 16777216

    // ---- expert path ----
    sgemm_kernel<<<grid_up, blk>>>(X, Wi0, C0, D_FF, D_MODEL, lbl, exp_stride);
    sgemm_kernel<<<grid_up, blk>>>(X, Wi1, C1, D_FF, D_MODEL, lbl, exp_stride);
    act_kernel<<<(unsigned)(nFF / 4 / 256), blk>>>(C0, C1, nFF);
    sgemm_kernel<<<grid_dn, blk>>>(C0, Wo, O0, D_MODEL, D_FF, lbl, exp_stride);

    // ---- shared path ----
    sgemm_kernel<<<grid_up, blk>>>(X, sWi0, C0, D_FF, D_MODEL, nullptr, 0);
    sgemm_kernel<<<grid_up, blk>>>(X, sWi1, C1, D_FF, D_MODEL, nullptr, 0);
    act_kernel<<<(unsigned)(nFF / 4 / 256), blk>>>(C0, C1, nFF);
    sgemm_kernel<<<grid_dn, blk>>>(C0, sWo, O1, D_MODEL, D_FF, nullptr, 0);

    // ---- gate + combine ----
    gate_kernel<<<BATCH, blk>>>(O0, O1, G0, G1, W);
    combine_kernel<<<(unsigned)(nD / 4 / 256), blk>>>(O0, O1, W, out);
}

// round 2
// speedup vs baseline: 2.8946x; 2.8946x over previous
#include <cuda_runtime.h>
#include <math.h>
#include <stdint.h>

#define D_MODEL 1024
#define D_FF    4096
#define BATCH   8
#define SEQ     2048
#define M_TOT   (BATCH * SEQ)   // 16384

// ---------------- scratch (allocation-free: __device__ globals) ----------------
__device__ float g_C0[(long long)M_TOT * D_FF];    // 256 MB: up-proj / H
__device__ float g_O0[(long long)M_TOT * D_MODEL]; // 64 MB: expert_out
__device__ float g_O1[(long long)M_TOT * D_MODEL]; // 64 MB: share_out
__device__ float g_W[BATCH * 2];                   // gate weights

// ---------------- helpers ------------------------------------------------------
__device__ __forceinline__ float to_tf32(float x) {
    float r;
    asm("cvt.rna.tf32.f32 %0, %1;" : "=f"(r) : "f"(x));
    return r;
}

__device__ __forceinline__ float gelu_tanh(float x) {
    float x3 = x * x * x;
    return 0.5f * x * (1.f + tanhf(0.7978845608028654f * (x + 0.044715f * x3)));
}

__device__ __forceinline__ void mma_tf32(float* d, const uint32_t* a, const uint32_t* b) {
    asm volatile(
        "mma.sync.aligned.m16n8k8.row.col.f32.tf32.tf32.f32 "
        "{%0,%1,%2,%3}, {%4,%5,%6,%7}, {%8,%9}, {%0,%1,%2,%3};"
        : "+f"(d[0]), "+f"(d[1]), "+f"(d[2]), "+f"(d[3])
        : "r"(a[0]), "r"(a[1]), "r"(a[2]), "r"(a[3]), "r"(b[0]), "r"(b[1]));
}

// ---------------- TF32 tensor-core GEMM ----------------------------------------
// C[M,N] = A[M,K] @ B[K,N], row-major. Per-batch expert weight offset via labels.
// fuse==1: C[i] = gelu_tanh(gsrc[i]) * acc[i]  (gated-FFN activation fusion;
//          gsrc may alias C — same-element read then write from same thread).
#define BM 128
#define BN 128
#define BK 16
#define A_STRIDE 20    // BK + 4 pad -> conflict-free fragment loads
#define B_STRIDE 136   // BN + 8 pad -> conflict-free fragment loads

__global__ __launch_bounds__(256)
void tf32_gemm_kernel(const float* __restrict__ A, const float* __restrict__ B,
                      float* __restrict__ C, const float* __restrict__ gsrc,
                      int N, int K, const int* __restrict__ labels,
                      long long expert_stride, int fuse)
{
    __shared__ float Am[2][BM][A_STRIDE];
    __shared__ float Bs[2][BK][B_STRIDE];

    const int tid  = threadIdx.x;
    const int lane = tid & 31;
    const int warp = tid >> 5;
    const int lr   = lane >> 2;   // 0..7
    const int lc   = lane & 3;    // 0..3

    const int warp_m = warp >> 1;           // 0..3
    const int warp_n = warp & 1;            // 0..1
    const int wmBase = warp_m * 32;
    const int wnBase = warp_n * 64;

    const int rowBase = blockIdx.y * BM;
    const int colBase = blockIdx.x * BN;

    const float* Bp = B;
    if (labels) {
        int b = rowBase / SEQ;              // BM divides SEQ: no straddle
        Bp += (long long)labels[b] * expert_stride;
    }

    // global-load thread mappings (2 float4 per thread per tile, each matrix)
    // A tile: 128 rows x 16 cols = 512 float4
    const int aRow0 = tid >> 2,               aC40 = (tid & 3) * 4;
    const int aRow1 = (tid + 256) >> 2,       aC41 = ((tid + 256) & 3) * 4;
    // B tile: 16 rows x 128 cols = 512 float4
    const int bRow0 = tid >> 5,               bC40 = (tid & 31) * 4;
    const int bRow1 = (tid + 256) >> 5,       bC41 = ((tid + 256) & 31) * 4;

    float acc[2][8][4];
#pragma unroll
    for (int mt = 0; mt < 2; mt++)
#pragma unroll
        for (int nt = 0; nt < 8; nt++)
#pragma unroll
            for (int i = 0; i < 4; i++) acc[mt][nt][i] = 0.f;

    const int ntiles = K / BK;

    // ---- prologue: stage tile 0 ----
    {
        float4 a0 = *reinterpret_cast<const float4*>(&A[(long long)(rowBase + aRow0) * K + aC40]);
        float4 a1 = *reinterpret_cast<const float4*>(&A[(long long)(rowBase + aRow1) * K + aC41]);
        float4 b0 = *reinterpret_cast<const float4*>(&Bp[(long long)bRow0 * N + colBase + bC40]);
        float4 b1 = *reinterpret_cast<const float4*>(&Bp[(long long)bRow1 * N + colBase + bC41]);
        float4* pa0 = reinterpret_cast<float4*>(&Am[0][aRow0][aC40]);
        float4* pa1 = reinterpret_cast<float4*>(&Am[0][aRow1][aC41]);
        *pa0 = make_float4(to_tf32(a0.x), to_tf32(a0.y), to_tf32(a0.z), to_tf32(a0.w));
        *pa1 = make_float4(to_tf32(a1.x), to_tf32(a1.y), to_tf32(a1.z), to_tf32(a1.w));
        float4* pb0 = reinterpret_cast<float4*>(&Bs[0][bRow0][bC40]);
        float4* pb1 = reinterpret_cast<float4*>(&Bs[0][bRow1][bC41]);
        *pb0 = make_float4(to_tf32(b0.x), to_tf32(b0.y), to_tf32(b0.z), to_tf32(b0.w));
        *pb1 = make_float4(to_tf32(b1.x), to_tf32(b1.y), to_tf32(b1.z), to_tf32(b1.w));
    }
    __syncthreads();

    for (int t = 0; t < ntiles; t++) {
        const int buf = t & 1;
        float4 a0, a1, b0, b1;
        const bool more = (t + 1 < ntiles);
        if (more) {
            const int k0 = (t + 1) * BK;
            a0 = *reinterpret_cast<const float4*>(&A[(long long)(rowBase + aRow0) * K + k0 + aC40]);
            a1 = *reinterpret_cast<const float4*>(&A[(long long)(rowBase + aRow1) * K + k0 + aC41]);
            b0 = *reinterpret_cast<const float4*>(&Bp[(long long)(k0 + bRow0) * N + colBase + bC40]);
            b1 = *reinterpret_cast<const float4*>(&Bp[(long long)(k0 + bRow1) * N + colBase + bC41]);
        }

        // ---- compute on current buffer: 2 k8-steps ----
#pragma unroll
        for (int ks = 0; ks < 2; ks++) {
            const int k8 = ks * 8;
            uint32_t afr[2][4], bfr[8][2];
#pragma unroll
            for (int mt = 0; mt < 2; mt++) {
                const int r = wmBase + mt * 16 + lr;
                afr[mt][0] = __float_as_uint(Am[buf][r    ][k8 + lc]);
                afr[mt][1] = __float_as_uint(Am[buf][r + 8][k8 + lc]);
                afr[mt][2] = __float_as_uint(Am[buf][r    ][k8 + lc + 4]);
                afr[mt][3] = __float_as_uint(Am[buf][r + 8][k8 + lc + 4]);
            }
#pragma unroll
            for (int nt = 0; nt < 8; nt++) {
                const int c = wnBase + nt * 8 + lr;
                bfr[nt][0] = __float_as_uint(Bs[buf][k8 + lc    ][c]);
                bfr[nt][1] = __float_as_uint(Bs[buf][k8 + lc + 4][c]);
            }
#pragma unroll
            for (int mt = 0; mt < 2; mt++)
#pragma unroll
                for (int nt = 0; nt < 8; nt++)
                    mma_tf32(acc[mt][nt], afr[mt], bfr[nt]);
        }

        if (more) {
            const int nbuf = buf ^ 1;
            float4* pa0 = reinterpret_cast<float4*>(&Am[nbuf][aRow0][aC40]);
            float4* pa1 = reinterpret_cast<float4*>(&Am[nbuf][aRow1][aC41]);
            *pa0 = make_float4(to_tf32(a0.x), to_tf32(a0.y), to_tf32(a0.z), to_tf32(a0.w));
            *pa1 = make_float4(to_tf32(a1.x), to_tf32(a1.y), to_tf32(a1.z), to_tf32(a1.w));
            float4* pb0 = reinterpret_cast<float4*>(&Bs[nbuf][bRow0][bC40]);
            float4* pb1 = reinterpret_cast<float4*>(&Bs[nbuf][bRow1][bC41]);
            *pb0 = make_float4(to_tf32(b0.x), to_tf32(b0.y), to_tf32(b0.z), to_tf32(b0.w));
            *pb1 = make_float4(to_tf32(b1.x), to_tf32(b1.y), to_tf32(b1.z), to_tf32(b1.w));
        }
        __syncthreads();
    }

    // ---- epilogue ----
#pragma unroll
    for (int mt = 0; mt < 2; mt++) {
        const int r0 = rowBase + wmBase + mt * 16 + lr;
#pragma unroll
        for (int nt = 0; nt < 8; nt++) {
            const int c = colBase + wnBase + nt * 8 + lc * 2;
            long long i0 = (long long)r0 * N + c;
            long long i1 = (long long)(r0 + 8) * N + c;
            if (fuse) {
                float2 g0 = *reinterpret_cast<const float2*>(&gsrc[i0]);
                float2 g1 = *reinterpret_cast<const float2*>(&gsrc[i1]);
                float2 v0 = make_float2(gelu_tanh(g0.x) * acc[mt][nt][0],
                                        gelu_tanh(g0.y) * acc[mt][nt][1]);
                float2 v1 = make_float2(gelu_tanh(g1.x) * acc[mt][nt][2],
                                        gelu_tanh(g1.y) * acc[mt][nt][3]);
                *reinterpret_cast<float2*>(&C[i0]) = v0;
                *reinterpret_cast<float2*>(&C[i1]) = v1;
            } else {
                *reinterpret_cast<float2*>(&C[i0]) =
                    make_float2(acc[mt][nt][0], acc[mt][nt][1]);
                *reinterpret_cast<float2*>(&C[i1]) =
                    make_float2(acc[mt][nt][2], acc[mt][nt][3]);
            }
        }
    }
}

// ---------------- gate: weights[b][2] from first-token rows --------------------
__global__ __launch_bounds__(256)
void gate_kernel(const float* __restrict__ O0, const float* __restrict__ O1,
                 const float* __restrict__ g0, const float* __restrict__ g1,
                 float* __restrict__ w)
{
    int b = blockIdx.x;
    const float* r0 = O0 + (long long)b * SEQ * D_MODEL;
    const float* r1 = O1 + (long long)b * SEQ * D_MODEL;

    float h[4] = {0.f, 0.f, 0.f, 0.f};
    for (int k = 0; k < 2 * D_MODEL; k++) {
        float xin = (k < D_MODEL) ? r0[k] : r1[k - D_MODEL];
        const float* grow = g0 + (long long)k * D_MODEL;
#pragma unroll
        for (int u = 0; u < 4; u++)
            h[u] = fmaf(xin, grow[threadIdx.x + 256 * u], h[u]);
    }

    float l0 = 0.f, l1 = 0.f;
#pragma unroll
    for (int u = 0; u < 4; u++) {
        int j = threadIdx.x + 256 * u;
        float hr = fmaxf(h[u], 0.f);
        l0 = fmaf(hr, g1[j * 2 + 0], l0);
        l1 = fmaf(hr, g1[j * 2 + 1], l1);
    }

    __shared__ float red0[256], red1[256];
    red0[threadIdx.x] = l0;
    red1[threadIdx.x] = l1;
    __syncthreads();
    for (int s = 128; s > 0; s >>= 1) {
        if (threadIdx.x < s) {
            red0[threadIdx.x] += red0[threadIdx.x + s];
            red1[threadIdx.x] += red1[threadIdx.x + s];
        }
        __syncthreads();
    }
    if (threadIdx.x == 0) {
        float a = red0[0], c = red1[0];
        float m  = fmaxf(a, c);
        float e0 = expf(a - m), e1 = expf(c - m);
        float inv = 1.f / (e0 + e1);
        w[b * 2 + 0] = e0 * inv;
        w[b * 2 + 1] = e1 * inv;
    }
}

// ---------------- combine: out = O0*w0[b] + O1*w1[b] ---------------------------
__global__ __launch_bounds__(256)
void combine_kernel(const float* __restrict__ O0, const float* __restrict__ O1,
                    const float* __restrict__ w, float* __restrict__ out)
{
    long long i = ((long long)blockIdx.x * blockDim.x + threadIdx.x) * 4;
    int b = (int)(i / ((long long)SEQ * D_MODEL));
    float w0 = w[b * 2 + 0], w1 = w[b * 2 + 1];
    float4 a = *reinterpret_cast<const float4*>(&O0[i]);
    float4 c = *reinterpret_cast<const float4*>(&O1[i]);
    a.x = a.x * w0 + c.x * w1;
    a.y = a.y * w0 + c.y * w1;
    a.z = a.z * w0 + c.z * w1;
    a.w = a.w * w0 + c.w * w1;
    *reinterpret_cast<float4*>(&out[i]) = a;
}

// ---------------- launch -------------------------------------------------------
extern "C" void kernel_launch(void* const* d_in, const int* in_sizes, int n_in,
                              void* d_out, int out_size)
{
    const float* X    = (const float*)d_in[0];
    const int*   lbl  = (const int*)  d_in[1];
    const float* Wi0  = (const float*)d_in[2];
    const float* Wi1  = (const float*)d_in[3];
    const float* Wo   = (const float*)d_in[4];
    const float* sWi0 = (const float*)d_in[5];
    const float* sWi1 = (const float*)d_in[6];
    const float* sWo  = (const float*)d_in[7];
    const float* G0   = (const float*)d_in[8];
    const float* G1   = (const float*)d_in[9];
    float* out = (float*)d_out;

    float *C0, *O0, *O1, *W;
    cudaGetSymbolAddress((void**)&C0, g_C0);
    cudaGetSymbolAddress((void**)&O0, g_O0);
    cudaGetSymbolAddress((void**)&O1, g_O1);
    cudaGetSymbolAddress((void**)&W,  g_W);

    const long long exp_stride = (long long)D_MODEL * D_FF;
    dim3 blk(256);
    dim3 grid_up(D_FF / BN, M_TOT / BM);     // (32,128)
    dim3 grid_dn(D_MODEL / BN, M_TOT / BM);  // (8,128)
    const long long nD = (long long)M_TOT * D_MODEL;

    // ---- expert path ----
    tf32_gemm_kernel<<<grid_up, blk>>>(X, Wi0, C0, nullptr, D_FF, D_MODEL, lbl, exp_stride, 0);
    tf32_gemm_kernel<<<grid_up, blk>>>(X, Wi1, C0, C0,      D_FF, D_MODEL, lbl, exp_stride, 1);
    tf32_gemm_kernel<<<grid_dn, blk>>>(C0, Wo,  O0, nullptr, D_MODEL, D_FF, lbl, exp_stride, 0);

    // ---- shared path ----
    tf32_gemm_kernel<<<grid_up, blk>>>(X, sWi0, C0, nullptr, D_FF, D_MODEL, nullptr, 0, 0);
    tf32_gemm_kernel<<<grid_up, blk>>>(X, sWi1, C0, C0,      D_FF, D_MODEL, nullptr, 0, 1);
    tf32_gemm_kernel<<<grid_dn, blk>>>(C0, sWo, O1, nullptr, D_MODEL, D_FF, nullptr, 0, 0);

    // ---- gate + combine ----
    gate_kernel<<<BATCH, blk>>>(O0, O1, G0, G1, W);
    combine_kernel<<<(unsigned)(nD / 4 / 256), blk>>>(O0, O1, W, out);
}

// round 4
// speedup vs baseline: 7.5459x; 2.6069x over previous
#include <cuda_runtime.h>
#include <cuda_fp16.h>
#include <math.h>
#include <stdint.h>

#define D_MODEL 1024
#define D_FF    4096
#define BATCH   8
#define SEQ     2048
#define M_TOT   (BATCH * SEQ)   // 16384

// ---------------- scratch (allocation-free: __device__ globals) ----------------
__device__ __half g_Xh[(size_t)M_TOT * D_MODEL];     // 32 MB  fp16 X
__device__ __half g_H [(size_t)M_TOT * D_FF];        // 128 MB fp16 g then H
__device__ __half g_Wh[(size_t)5 * D_MODEL * D_FF];  // 40 MB  fp16 weights (reused)
__device__ float  g_O0[(size_t)M_TOT * D_MODEL];     // 64 MB  expert_out
__device__ float  g_O1[(size_t)M_TOT * D_MODEL];     // 64 MB  share_out
__device__ float  g_W [BATCH * 2];                   // gate weights

// ---------------- helpers ------------------------------------------------------
__device__ __forceinline__ uint32_t smem_u32(const void* p) {
    uint32_t a;
    asm("{ .reg .u64 t; cvta.to.shared.u64 t, %1; cvt.u32.u64 %0, t; }"
        : "=r"(a) : "l"(p));
    return a;
}

__device__ __forceinline__ float gelu_tanh(float x) {
    float x3 = x * x * x;
    return 0.5f * x * (1.f + tanhf(0.7978845608028654f * (x + 0.044715f * x3)));
}

__device__ __forceinline__ void cp_async16(uint32_t saddr, const void* gaddr) {
    asm volatile("cp.async.cg.shared.global [%0], [%1], 16;"
                 :: "r"(saddr), "l"(gaddr) : "memory");
}
#define CP_COMMIT() asm volatile("cp.async.commit_group;" ::: "memory")
#define CP_WAIT1()  asm volatile("cp.async.wait_group 1;" ::: "memory")

__device__ __forceinline__ void ldsm4(uint32_t* r, uint32_t addr) {
    asm volatile("ldmatrix.sync.aligned.m8n8.x4.shared.b16 {%0,%1,%2,%3}, [%4];"
                 : "=r"(r[0]), "=r"(r[1]), "=r"(r[2]), "=r"(r[3]) : "r"(addr));
}
__device__ __forceinline__ void ldsm4t(uint32_t* r, uint32_t addr) {
    asm volatile("ldmatrix.sync.aligned.m8n8.x4.trans.shared.b16 {%0,%1,%2,%3}, [%4];"
                 : "=r"(r[0]), "=r"(r[1]), "=r"(r[2]), "=r"(r[3]) : "r"(addr));
}
__device__ __forceinline__ void mma16816(float* d, const uint32_t* a, const uint32_t* b) {
    asm volatile(
        "mma.sync.aligned.m16n8k16.row.col.f32.f16.f16.f32 "
        "{%0,%1,%2,%3}, {%4,%5,%6,%7}, {%8,%9}, {%0,%1,%2,%3};"
        : "+f"(d[0]), "+f"(d[1]), "+f"(d[2]), "+f"(d[3])
        : "r"(a[0]), "r"(a[1]), "r"(a[2]), "r"(a[3]), "r"(b[0]), "r"(b[1]));
}

// ---------------- fp16 tensor-core GEMM ----------------------------------------
// C[M,N] = A[M,K] @ B[K,N]; A,B fp16 row-major, C fp32 or fp16.
// FUSE: C = half(gelu(gsrc) * acc)  (gsrc may alias C; same-thread same-element RMW)
#define BM 128
#define BN 128
#define BKH 64                         // k halves per stage
#define STAGES 3
#define A_BYTES 16384                  // 128 rows x 128 B
#define STAGE_BYTES 32768
#define GEMM_SMEM (STAGES * STAGE_BYTES)

template<int K>
__device__ __forceinline__ void fill_stage(uint32_t st, const __half* __restrict__ A,
                                           const __half* __restrict__ Bp,
                                           int rowBase, int colBase, int k0,
                                           int N, int tid)
{
#pragma unroll
    for (int i = 0; i < 4; i++) {      // A: 128 rows x 8 16B-chunks
        int c = tid + i * 256;
        int row = c >> 3, kc = c & 7;
        uint32_t dst = st + (row << 7) + ((kc ^ (row & 7)) << 4);
        cp_async16(dst, A + (size_t)(rowBase + row) * K + k0 + (kc << 3));
    }
#pragma unroll
    for (int i = 0; i < 4; i++) {      // B: 64 rows x 16 16B-chunks
        int c = tid + i * 256;
        int row = c >> 4, nc = c & 15;
        uint32_t dst = st + A_BYTES + (row << 8) +
                       ((((nc ^ row) & 7) | (nc & 8)) << 4);
        cp_async16(dst, Bp + (size_t)(k0 + row) * N + colBase + (nc << 3));
    }
}

template<int K, bool FUSE, bool OUTH>
__global__ __launch_bounds__(256, 2)
void hgemm(const __half* __restrict__ A, const __half* __restrict__ Bw,
           void* __restrict__ Cv, const __half* __restrict__ gsrc,
           int N, const int* __restrict__ labels, size_t estride)
{
    extern __shared__ char smem[];
    const uint32_t sb = smem_u32(smem);
    const int tid = threadIdx.x, lane = tid & 31, warp = tid >> 5;
    const int rowBase = blockIdx.y * BM, colBase = blockIdx.x * BN;
    const __half* Bp = Bw + (labels ? (size_t)labels[rowBase / SEQ] * estride : 0);

    const int wm = (warp >> 1) * 32, wn = (warp & 1) * 64;
    const int lr = lane >> 2, lc = lane & 3;

    float acc[2][8][4];
#pragma unroll
    for (int mt = 0; mt < 2; mt++)
#pragma unroll
        for (int nt = 0; nt < 8; nt++)
#pragma unroll
            for (int i = 0; i < 4; i++) acc[mt][nt][i] = 0.f;

    // ldmatrix address precompute
    const int aRow = wm + (lane & 15);
    const uint32_t aOff = (uint32_t)aRow << 7;
    const uint32_t a_r7 = aRow & 7;
    const int hi = lane >> 4;
    const uint32_t bRowOff = (uint32_t)(lane & 15) << 8;
    const uint32_t b_r7 = lane & 7;
    uint32_t ncSw[4];
#pragma unroll
    for (int p = 0; p < 4; p++) {
        int nchunk = (wn >> 3) + p * 2 + hi;
        ncSw[p] = (uint32_t)((nchunk & 8) | ((nchunk ^ b_r7) & 7)) << 4;
    }

    const int T = K / BKH;
    fill_stage<K>(sb, A, Bp, rowBase, colBase, 0, N, tid);            CP_COMMIT();
    fill_stage<K>(sb + STAGE_BYTES, A, Bp, rowBase, colBase, BKH, N, tid); CP_COMMIT();

    int buf = 0;
    for (int t = 0; t < T; t++) {
        CP_WAIT1();
        __syncthreads();
        const uint32_t base  = sb + (uint32_t)buf * STAGE_BYTES;
        const uint32_t aBase = base + aOff;
        const uint32_t bBase = base + A_BYTES + bRowOff;
#pragma unroll
        for (int ks = 0; ks < 4; ks++) {
            uint32_t a[2][4], b[4][4];
            const uint32_t csw = (((ks * 2 + hi) ^ a_r7) << 4);
            ldsm4(a[0], aBase + csw);
            ldsm4(a[1], aBase + (16u << 7) + csw);
            const uint32_t bk = bBase + (uint32_t)ks * 4096;
#pragma unroll
            for (int p = 0; p < 4; p++) ldsm4t(b[p], bk + ncSw[p]);
#pragma unroll
            for (int mt = 0; mt < 2; mt++)
#pragma unroll
                for (int nt = 0; nt < 8; nt++)
                    mma16816(acc[mt][nt], a[mt], &b[nt >> 1][(nt & 1) * 2]);
        }
        const int tn = t + 2;
        if (tn < T) {
            int nb = buf + 2; if (nb >= 3) nb -= 3;
            fill_stage<K>(sb + (uint32_t)nb * STAGE_BYTES, A, Bp,
                          rowBase, colBase, tn * BKH, N, tid);
        }
        CP_COMMIT();
        buf++; if (buf == 3) buf = 0;
    }

    // ---- epilogue ----
#pragma unroll
    for (int mt = 0; mt < 2; mt++) {
        const int r0 = rowBase + wm + mt * 16 + lr;
#pragma unroll
        for (int nt = 0; nt < 8; nt++) {
            const int c = colBase + wn + nt * 8 + lc * 2;
            const size_t i0 = (size_t)r0 * N + c;
            const size_t i1 = i0 + (size_t)8 * N;
            float v0 = acc[mt][nt][0], v1 = acc[mt][nt][1];
            float v2 = acc[mt][nt][2], v3 = acc[mt][nt][3];
            if (OUTH) {
                __half* C = (__half*)Cv;
                if (FUSE) {
                    __half2 ga = *(const __half2*)(gsrc + i0);
                    __half2 gb = *(const __half2*)(gsrc + i1);
                    v0 *= gelu_tanh(__low2float(ga));
                    v1 *= gelu_tanh(__high2float(ga));
                    v2 *= gelu_tanh(__low2float(gb));
                    v3 *= gelu_tanh(__high2float(gb));
                }
                *(__half2*)(C + i0) = __floats2half2_rn(v0, v1);
                *(__half2*)(C + i1) = __floats2half2_rn(v2, v3);
            } else {
                float* C = (float*)Cv;
                *(float2*)(C + i0) = make_float2(v0, v1);
                *(float2*)(C + i1) = make_float2(v2, v3);
            }
        }
    }
}

// ---------------- f32 -> f16 conversion ----------------------------------------
__global__ __launch_bounds__(256)
void cvt_f16(const float* __restrict__ in, __half* __restrict__ out, size_t n)
{
    size_t i = ((size_t)blockIdx.x * 256 + threadIdx.x) * 8;
    if (i >= n) return;
    float4 v0 = *(const float4*)(in + i);
    float4 v1 = *(const float4*)(in + i + 4);
    __half2* o = (__half2*)(out + i);
    o[0] = __floats2half2_rn(v0.x, v0.y);
    o[1] = __floats2half2_rn(v0.z, v0.w);
    o[2] = __floats2half2_rn(v1.x, v1.y);
    o[3] = __floats2half2_rn(v1.z, v1.w);
}

// ---------------- gate: weights[b][2] from first-token rows --------------------
__global__ __launch_bounds__(256)
void gate_kernel(const float* __restrict__ O0, const float* __restrict__ O1,
                 const float* __restrict__ g0, const float* __restrict__ g1,
                 float* __restrict__ w)
{
    int b = blockIdx.x;
    const float* r0 = O0 + (size_t)b * SEQ * D_MODEL;
    const float* r1 = O1 + (size_t)b * SEQ * D_MODEL;

    float h[4] = {0.f, 0.f, 0.f, 0.f};
    for (int k = 0; k < 2 * D_MODEL; k++) {
        float xin = (k < D_MODEL) ? r0[k] : r1[k - D_MODEL];
        const float* grow = g0 + (size_t)k * D_MODEL;
#pragma unroll
        for (int u = 0; u < 4; u++)
            h[u] = fmaf(xin, grow[threadIdx.x + 256 * u], h[u]);
    }
    float l0 = 0.f, l1 = 0.f;
#pragma unroll
    for (int u = 0; u < 4; u++) {
        int j = threadIdx.x + 256 * u;
        float hr = fmaxf(h[u], 0.f);
        l0 = fmaf(hr, g1[j * 2 + 0], l0);
        l1 = fmaf(hr, g1[j * 2 + 1], l1);
    }
    __shared__ float red0[256], red1[256];
    red0[threadIdx.x] = l0;
    red1[threadIdx.x] = l1;
    __syncthreads();
    for (int s = 128; s > 0; s >>= 1) {
        if (threadIdx.x < s) {
            red0[threadIdx.x] += red0[threadIdx.x + s];
            red1[threadIdx.x] += red1[threadIdx.x + s];
        }
        __syncthreads();
    }
    if (threadIdx.x == 0) {
        float a = red0[0], c = red1[0];
        float m  = fmaxf(a, c);
        float e0 = expf(a - m), e1 = expf(c - m);
        float inv = 1.f / (e0 + e1);
        w[b * 2 + 0] = e0 * inv;
        w[b * 2 + 1] = e1 * inv;
    }
}

// ---------------- combine ------------------------------------------------------
__global__ __launch_bounds__(256)
void combine_kernel(const float* __restrict__ O0, const float* __restrict__ O1,
                    const float* __restrict__ w, float* __restrict__ out)
{
    long long i = ((long long)blockIdx.x * blockDim.x + threadIdx.x) * 4;
    int b = (int)(i / ((long long)SEQ * D_MODEL));
    float w0 = w[b * 2 + 0], w1 = w[b * 2 + 1];
    float4 a = *reinterpret_cast<const float4*>(&O0[i]);
    float4 c = *reinterpret_cast<const float4*>(&O1[i]);
    a.x = a.x * w0 + c.x * w1;
    a.y = a.y * w0 + c.y * w1;
    a.z = a.z * w0 + c.z * w1;
    a.w = a.w * w0 + c.w * w1;
    *reinterpret_cast<float4*>(&out[i]) = a;
}

// ---------------- launch -------------------------------------------------------
extern "C" void kernel_launch(void* const* d_in, const int* in_sizes, int n_in,
                              void* d_out, int out_size)
{
    const float* X    = (const float*)d_in[0];
    const int*   lbl  = (const int*)  d_in[1];
    const float* Wi0  = (const float*)d_in[2];
    const float* Wi1  = (const float*)d_in[3];
    const float* Wo   = (const float*)d_in[4];
    const float* sWi0 = (const float*)d_in[5];
    const float* sWi1 = (const float*)d_in[6];
    const float* sWo  = (const float*)d_in[7];
    const float* G0   = (const float*)d_in[8];
    const float* G1   = (const float*)d_in[9];
    float* out = (float*)d_out;

    __half *Xh, *H, *Wh;
    float *O0, *O1, *W;
    cudaGetSymbolAddress((void**)&Xh, g_Xh);
    cudaGetSymbolAddress((void**)&H,  g_H);
    cudaGetSymbolAddress((void**)&Wh, g_Wh);
    cudaGetSymbolAddress((void**)&O0, g_O0);
    cudaGetSymbolAddress((void**)&O1, g_O1);
    cudaGetSymbolAddress((void**)&W,  g_W);

    cudaFuncSetAttribute(hgemm<1024, false, true>,
                         cudaFuncAttributeMaxDynamicSharedMemorySize, GEMM_SMEM);
    cudaFuncSetAttribute(hgemm<1024, true, true>,
                         cudaFuncAttributeMaxDynamicSharedMemorySize, GEMM_SMEM);
    cudaFuncSetAttribute(hgemm<4096, false, false>,
                         cudaFuncAttributeMaxDynamicSharedMemorySize, GEMM_SMEM);

    const size_t estride = (size_t)D_MODEL * D_FF;
    const size_t nX = (size_t)M_TOT * D_MODEL;
    const size_t nWe = (size_t)5 * D_MODEL * D_FF;   // expert weight tensor
    const size_t nWs = (size_t)D_MODEL * D_FF;       // shared weight tensor
    dim3 blk(256);
    dim3 grid_up(D_FF / BN, M_TOT / BM);     // (32,128)
    dim3 grid_dn(D_MODEL / BN, M_TOT / BM);  // (8,128)

    cvt_f16<<<(unsigned)(nX / 2048), blk>>>(X, Xh, nX);

    // ---- expert path ----
    cvt_f16<<<(unsigned)(nWe / 2048), blk>>>(Wi0, Wh, nWe);
    hgemm<1024, false, true><<<grid_up, blk, GEMM_SMEM>>>(Xh, Wh, H, nullptr, D_FF, lbl, estride);
    cvt_f16<<<(unsigned)(nWe / 2048), blk>>>(Wi1, Wh, nWe);
    hgemm<1024, true, true><<<grid_up, blk, GEMM_SMEM>>>(Xh, Wh, H, H, D_FF, lbl, estride);
    cvt_f16<<<(unsigned)(nWe / 2048), blk>>>(Wo, Wh, nWe);
    hgemm<4096, false, false><<<grid_dn, blk, GEMM_SMEM>>>(H, Wh, O0, nullptr, D_MODEL, lbl, estride);

    // ---- shared path ----
    cvt_f16<<<(unsigned)(nWs / 2048), blk>>>(sWi0, Wh, nWs);
    hgemm<1024, false, true><<<grid_up, blk, GEMM_SMEM>>>(Xh, Wh, H, nullptr, D_FF, nullptr, 0);
    cvt_f16<<<(unsigned)(nWs / 2048), blk>>>(sWi1, Wh, nWs);
    hgemm<1024, true, true><<<grid_up, blk, GEMM_SMEM>>>(Xh, Wh, H, H, D_FF, nullptr, 0);
    cvt_f16<<<(unsigned)(nWs / 2048), blk>>>(sWo, Wh, nWs);
    hgemm<4096, false, false><<<grid_dn, blk, GEMM_SMEM>>>(H, Wh, O1, nullptr, D_MODEL, nullptr, 0);

    // ---- gate + combine ----
    gate_kernel<<<BATCH, blk>>>(O0, O1, G0, G1, W);
    combine_kernel<<<(unsigned)(nX / 4 / 256), blk>>>(O0, O1, W, out);
}

// round 5
// speedup vs baseline: 7.7500x; 1.0270x over previous
#include <cuda_runtime.h>
#include <cuda_fp16.h>
#include <math.h>
#include <stdint.h>

#define D_MODEL 1024
#define D_FF    4096
#define BATCH   8
#define SEQ     2048
#define M_TOT   (BATCH * SEQ)   // 16384

// ---------------- scratch (allocation-free: __device__ globals) ----------------
__device__ __half g_Xh[(size_t)M_TOT * D_MODEL];     // 32 MB  fp16 X
__device__ __half g_H [(size_t)M_TOT * D_FF];        // 128 MB fp16 g then H
__device__ __half g_Wh[(size_t)5 * D_MODEL * D_FF];  // 40 MB  fp16 weights (reused)
__device__ float  g_O0[(size_t)M_TOT * D_MODEL];     // 64 MB  expert_out
__device__ float  g_O1[(size_t)M_TOT * D_MODEL];     // 64 MB  share_out
__device__ float  g_W [BATCH * 2];                   // gate weights

// ---------------- helpers ------------------------------------------------------
__device__ __forceinline__ uint32_t smem_u32(const void* p) {
    uint32_t a;
    asm("{ .reg .u64 t; cvta.to.shared.u64 t, %1; cvt.u32.u64 %0, t; }"
        : "=r"(a) : "l"(p));
    return a;
}

__device__ __forceinline__ float gelu_tanh(float x) {
    float x3 = x * x * x;
    return 0.5f * x * (1.f + tanhf(0.7978845608028654f * (x + 0.044715f * x3)));
}

__device__ __forceinline__ void cp_async16(uint32_t saddr, const void* gaddr) {
    asm volatile("cp.async.cg.shared.global [%0], [%1], 16;"
                 :: "r"(saddr), "l"(gaddr) : "memory");
}
#define CP_COMMIT() asm volatile("cp.async.commit_group;" ::: "memory")
#define CP_WAIT1()  asm volatile("cp.async.wait_group 1;" ::: "memory")

__device__ __forceinline__ void ldsm4(uint32_t* r, uint32_t addr) {
    asm volatile("ldmatrix.sync.aligned.m8n8.x4.shared.b16 {%0,%1,%2,%3}, [%4];"
                 : "=r"(r[0]), "=r"(r[1]), "=r"(r[2]), "=r"(r[3]) : "r"(addr));
}
__device__ __forceinline__ void ldsm4t(uint32_t* r, uint32_t addr) {
    asm volatile("ldmatrix.sync.aligned.m8n8.x4.trans.shared.b16 {%0,%1,%2,%3}, [%4];"
                 : "=r"(r[0]), "=r"(r[1]), "=r"(r[2]), "=r"(r[3]) : "r"(addr));
}
__device__ __forceinline__ void mma16816(float* d, const uint32_t* a, const uint32_t* b) {
    asm volatile(
        "mma.sync.aligned.m16n8k16.row.col.f32.f16.f16.f32 "
        "{%0,%1,%2,%3}, {%4,%5,%6,%7}, {%8,%9}, {%0,%1,%2,%3};"
        : "+f"(d[0]), "+f"(d[1]), "+f"(d[2]), "+f"(d[3])
        : "r"(a[0]), "r"(a[1]), "r"(a[2]), "r"(a[3]), "r"(b[0]), "r"(b[1]));
}

// ---------------- fp16 tensor-core GEMM ----------------------------------------
// C[M,N] = A[M,K] @ B[K,N]; A,B fp16 row-major, C fp32 or fp16.
// FUSE: C = half(gelu(gsrc) * acc)  (gsrc may alias C; same-thread same-element RMW)
#define BM 128
#define BN 128
#define BKH 64                         // k halves per stage
#define STAGES 3
#define A_BYTES 16384                  // 128 rows x 128 B
#define STAGE_BYTES 32768
#define GEMM_SMEM (STAGES * STAGE_BYTES)

template<int K>
__device__ __forceinline__ void fill_stage(uint32_t st, const __half* __restrict__ A,
                                           const __half* __restrict__ Bp,
                                           int rowBase, int colBase, int k0,
                                           int N, int tid)
{
#pragma unroll
    for (int i = 0; i < 4; i++) {      // A: 128 rows x 8 16B-chunks
        int c = tid + i * 256;
        int row = c >> 3, kc = c & 7;
        uint32_t dst = st + (row << 7) + ((kc ^ (row & 7)) << 4);
        cp_async16(dst, A + (size_t)(rowBase + row) * K + k0 + (kc << 3));
    }
#pragma unroll
    for (int i = 0; i < 4; i++) {      // B: 64 rows x 16 16B-chunks
        int c = tid + i * 256;
        int row = c >> 4, nc = c & 15;
        uint32_t dst = st + A_BYTES + (row << 8) +
                       ((((nc ^ row) & 7) | (nc & 8)) << 4);
        cp_async16(dst, Bp + (size_t)(k0 + row) * N + colBase + (nc << 3));
    }
}

__device__ __forceinline__ void load_frags(int ks, uint32_t a[2][4], uint32_t b[4][4],
                                           uint32_t aBase, uint32_t bBase,
                                           uint32_t a_r7, int hi,
                                           const uint32_t* ncSw)
{
    const uint32_t csw = (uint32_t)(((ks * 2 + hi) ^ (int)a_r7) << 4);
    ldsm4(a[0], aBase + csw);
    ldsm4(a[1], aBase + (16u << 7) + csw);
    const uint32_t bk = bBase + (uint32_t)ks * 4096;
#pragma unroll
    for (int p = 0; p < 4; p++) ldsm4t(b[p], bk + ncSw[p]);
}

template<int K, bool FUSE, bool OUTH>
__global__ __launch_bounds__(256, 2)
void hgemm(const __half* __restrict__ A, const __half* __restrict__ Bw,
           void* __restrict__ Cv, const __half* __restrict__ gsrc,
           int N, const int* __restrict__ labels, size_t estride)
{
    extern __shared__ char smem[];
    const uint32_t sb = smem_u32(smem);
    const int tid = threadIdx.x, lane = tid & 31, warp = tid >> 5;
    const int rowBase = blockIdx.y * BM, colBase = blockIdx.x * BN;
    const __half* Bp = Bw + (labels ? (size_t)labels[rowBase / SEQ] * estride : 0);

    const int wm = (warp >> 1) * 32, wn = (warp & 1) * 64;
    const int lr = lane >> 2, lc = lane & 3;

    float acc[2][8][4];
#pragma unroll
    for (int mt = 0; mt < 2; mt++)
#pragma unroll
        for (int nt = 0; nt < 8; nt++)
#pragma unroll
            for (int i = 0; i < 4; i++) acc[mt][nt][i] = 0.f;

    // ldmatrix address precompute
    const int aRow = wm + (lane & 15);
    const uint32_t aOff = (uint32_t)aRow << 7;
    const uint32_t a_r7 = aRow & 7;
    const int hi = lane >> 4;
    const uint32_t bRowOff = (uint32_t)(lane & 15) << 8;
    const uint32_t b_r7 = lane & 7;
    uint32_t ncSw[4];
#pragma unroll
    for (int p = 0; p < 4; p++) {
        int nchunk = (wn >> 3) + p * 2 + hi;
        ncSw[p] = (uint32_t)((nchunk & 8) | ((nchunk ^ b_r7) & 7)) << 4;
    }

    const int T = K / BKH;
    fill_stage<K>(sb, A, Bp, rowBase, colBase, 0, N, tid);                 CP_COMMIT();
    fill_stage<K>(sb + STAGE_BYTES, A, Bp, rowBase, colBase, BKH, N, tid); CP_COMMIT();

    int buf = 0;
    for (int t = 0; t < T; t++) {
        CP_WAIT1();
        __syncthreads();
        const uint32_t base  = sb + (uint32_t)buf * STAGE_BYTES;
        const uint32_t aBase = base + aOff;
        const uint32_t bBase = base + A_BYTES + bRowOff;

        // issue next-next stage fill FIRST so DRAM latency overlaps this stage's MMAs
        // (target buffer is the one retired at iteration t-1 -> safe after the sync)
        const int tn = t + 2;
        if (tn < T) {
            int nb = buf + 2; if (nb >= 3) nb -= 3;
            fill_stage<K>(sb + (uint32_t)nb * STAGE_BYTES, A, Bp,
                          rowBase, colBase, tn * BKH, N, tid);
        }
        CP_COMMIT();

        // fragment-pipelined compute: ldsm for ks+1 issues under ks's MMAs
        uint32_t afr[2][2][4], bfr[2][4][4];
        load_frags(0, afr[0], bfr[0], aBase, bBase, a_r7, hi, ncSw);
#pragma unroll
        for (int ks = 0; ks < 4; ks++) {
            const int cur = ks & 1;
            if (ks < 3)
                load_frags(ks + 1, afr[cur ^ 1], bfr[cur ^ 1],
                           aBase, bBase, a_r7, hi, ncSw);
#pragma unroll
            for (int mt = 0; mt < 2; mt++)
#pragma unroll
                for (int nt = 0; nt < 8; nt++)
                    mma16816(acc[mt][nt], afr[cur][mt],
                             &bfr[cur][nt >> 1][(nt & 1) * 2]);
        }
        buf++; if (buf == 3) buf = 0;
    }

    // ---- epilogue ----
#pragma unroll
    for (int mt = 0; mt < 2; mt++) {
        const int r0 = rowBase + wm + mt * 16 + lr;
#pragma unroll
        for (int nt = 0; nt < 8; nt++) {
            const int c = colBase + wn + nt * 8 + lc * 2;
            const size_t i0 = (size_t)r0 * N + c;
            const size_t i1 = i0 + (size_t)8 * N;
            float v0 = acc[mt][nt][0], v1 = acc[mt][nt][1];
            float v2 = acc[mt][nt][2], v3 = acc[mt][nt][3];
            if (OUTH) {
                __half* C = (__half*)Cv;
                if (FUSE) {
                    __half2 ga = *(const __half2*)(gsrc + i0);
                    __half2 gb = *(const __half2*)(gsrc + i1);
                    v0 *= gelu_tanh(__low2float(ga));
                    v1 *= gelu_tanh(__high2float(ga));
                    v2 *= gelu_tanh(__low2float(gb));
                    v3 *= gelu_tanh(__high2float(gb));
                }
                *(__half2*)(C + i0) = __floats2half2_rn(v0, v1);
                *(__half2*)(C + i1) = __floats2half2_rn(v2, v3);
            } else {
                float* C = (float*)Cv;
                *(float2*)(C + i0) = make_float2(v0, v1);
                *(float2*)(C + i1) = make_float2(v2, v3);
            }
        }
    }
}

// ---------------- f32 -> f16 conversion ----------------------------------------
__global__ __launch_bounds__(256)
void cvt_f16(const float* __restrict__ in, __half* __restrict__ out, size_t n)
{
    size_t i = ((size_t)blockIdx.x * 256 + threadIdx.x) * 8;
    if (i >= n) return;
    float4 v0 = *(const float4*)(in + i);
    float4 v1 = *(const float4*)(in + i + 4);
    __half2* o = (__half2*)(out + i);
    o[0] = __floats2half2_rn(v0.x, v0.y);
    o[1] = __floats2half2_rn(v0.z, v0.w);
    o[2] = __floats2half2_rn(v1.x, v1.y);
    o[3] = __floats2half2_rn(v1.z, v1.w);
}

// ---------------- gate: weights[b][2] from first-token rows --------------------
__global__ __launch_bounds__(256)
void gate_kernel(const float* __restrict__ O0, const float* __restrict__ O1,
                 const float* __restrict__ g0, const float* __restrict__ g1,
                 float* __restrict__ w)
{
    int b = blockIdx.x;
    const float* r0 = O0 + (size_t)b * SEQ * D_MODEL;
    const float* r1 = O1 + (size_t)b * SEQ * D_MODEL;

    float h[4] = {0.f, 0.f, 0.f, 0.f};
    for (int k = 0; k < 2 * D_MODEL; k++) {
        float xin = (k < D_MODEL) ? r0[k] : r1[k - D_MODEL];
        const float* grow = g0 + (size_t)k * D_MODEL;
#pragma unroll
        for (int u = 0; u < 4; u++)
            h[u] = fmaf(xin, grow[threadIdx.x + 256 * u], h[u]);
    }
    float l0 = 0.f, l1 = 0.f;
#pragma unroll
    for (int u = 0; u < 4; u++) {
        int j = threadIdx.x + 256 * u;
        float hr = fmaxf(h[u], 0.f);
        l0 = fmaf(hr, g1[j * 2 + 0], l0);
        l1 = fmaf(hr, g1[j * 2 + 1], l1);
    }
    __shared__ float red0[256], red1[256];
    red0[threadIdx.x] = l0;
    red1[threadIdx.x] = l1;
    __syncthreads();
    for (int s = 128; s > 0; s >>= 1) {
        if (threadIdx.x < s) {
            red0[threadIdx.x] += red0[threadIdx.x + s];
            red1[threadIdx.x] += red1[threadIdx.x + s];
        }
        __syncthreads();
    }
    if (threadIdx.x == 0) {
        float a = red0[0], c = red1[0];
        float m  = fmaxf(a, c);
        float e0 = expf(a - m), e1 = expf(c - m);
        float inv = 1.f / (e0 + e1);
        w[b * 2 + 0] = e0 * inv;
        w[b * 2 + 1] = e1 * inv;
    }
}

// ---------------- combine ------------------------------------------------------
__global__ __launch_bounds__(256)
void combine_kernel(const float* __restrict__ O0, const float* __restrict__ O1,
                    const float* __restrict__ w, float* __restrict__ out)
{
    long long i = ((long long)blockIdx.x * blockDim.x + threadIdx.x) * 4;
    int b = (int)(i / ((long long)SEQ * D_MODEL));
    float w0 = w[b * 2 + 0], w1 = w[b * 2 + 1];
    float4 a = *reinterpret_cast<const float4*>(&O0[i]);
    float4 c = *reinterpret_cast<const float4*>(&O1[i]);
    a.x = a.x * w0 + c.x * w1;
    a.y = a.y * w0 + c.y * w1;
    a.z = a.z * w0 + c.z * w1;
    a.w = a.w * w0 + c.w * w1;
    *reinterpret_cast<float4*>(&out[i]) = a;
}

// ---------------- launch -------------------------------------------------------
extern "C" void kernel_launch(void* const* d_in, const int* in_sizes, int n_in,
                              void* d_out, int out_size)
{
    const float* X    = (const float*)d_in[0];
    const int*   lbl  = (const int*)  d_in[1];
    const float* Wi0  = (const float*)d_in[2];
    const float* Wi1  = (const float*)d_in[3];
    const float* Wo   = (const float*)d_in[4];
    const float* sWi0 = (const float*)d_in[5];
    const float* sWi1 = (const float*)d_in[6];
    const float* sWo  = (const float*)d_in[7];
    const float* G0   = (const float*)d_in[8];
    const float* G1   = (const float*)d_in[9];
    float* out = (float*)d_out;

    __half *Xh, *H, *Wh;
    float *O0, *O1, *W;
    cudaGetSymbolAddress((void**)&Xh, g_Xh);
    cudaGetSymbolAddress((void**)&H,  g_H);
    cudaGetSymbolAddress((void**)&Wh, g_Wh);
    cudaGetSymbolAddress((void**)&O0, g_O0);
    cudaGetSymbolAddress((void**)&O1, g_O1);
    cudaGetSymbolAddress((void**)&W,  g_W);

    cudaFuncSetAttribute(hgemm<1024, false, true>,
                         cudaFuncAttributeMaxDynamicSharedMemorySize, GEMM_SMEM);
    cudaFuncSetAttribute(hgemm<1024, true, true>,
                         cudaFuncAttributeMaxDynamicSharedMemorySize, GEMM_SMEM);
    cudaFuncSetAttribute(hgemm<4096, false, false>,
                         cudaFuncAttributeMaxDynamicSharedMemorySize, GEMM_SMEM);

    const size_t estride = (size_t)D_MODEL * D_FF;
    const size_t nX = (size_t)M_TOT * D_MODEL;
    const size_t nWe = (size_t)5 * D_MODEL * D_FF;   // expert weight tensor
    const size_t nWs = (size_t)D_MODEL * D_FF;       // shared weight tensor
    dim3 blk(256);
    dim3 grid_up(D_FF / BN, M_TOT / BM);     // (32,128)
    dim3 grid_dn(D_MODEL / BN, M_TOT / BM);  // (8,128)

    cvt_f16<<<(unsigned)(nX / 2048), blk>>>(X, Xh, nX);

    // ---- expert path ----
    cvt_f16<<<(unsigned)(nWe / 2048), blk>>>(Wi0, Wh, nWe);
    hgemm<1024, false, true><<<grid_up, blk, GEMM_SMEM>>>(Xh, Wh, H, nullptr, D_FF, lbl, estride);
    cvt_f16<<<(unsigned)(nWe / 2048), blk>>>(Wi1, Wh, nWe);
    hgemm<1024, true, true><<<grid_up, blk, GEMM_SMEM>>>(Xh, Wh, H, H, D_FF, lbl, estride);
    cvt_f16<<<(unsigned)(nWe / 2048), blk>>>(Wo, Wh, nWe);
    hgemm<4096, false, false><<<grid_dn, blk, GEMM_SMEM>>>(H, Wh, O0, nullptr, D_MODEL, lbl, estride);

    // ---- shared path ----
    cvt_f16<<<(unsigned)(nWs / 2048), blk>>>(sWi0, Wh, nWs);
    hgemm<1024, false, true><<<grid_up, blk, GEMM_SMEM>>>(Xh, Wh, H, nullptr, D_FF, nullptr, 0);
    cvt_f16<<<(unsigned)(nWs / 2048), blk>>>(sWi1, Wh, nWs);
    hgemm<1024, true, true><<<grid_up, blk, GEMM_SMEM>>>(Xh, Wh, H, H, D_FF, nullptr, 0);
    cvt_f16<<<(unsigned)(nWs / 2048), blk>>>(sWo, Wh, nWs);
    hgemm<4096, false, false><<<grid_dn, blk, GEMM_SMEM>>>(H, Wh, O1, nullptr, D_MODEL, nullptr, 0);

    // ---- gate + combine ----
    gate_kernel<<<BATCH, blk>>>(O0, O1, G0, G1, W);
    combine_kernel<<<(unsigned)(nX / 4 / 256), blk>>>(O0, O1, W, out);
}